// round 13
// baseline (speedup 1.0000x reference)
#include <cuda_runtime.h>

// MaxPool3d k=2 s=2 fp32 [2,32,128,128,128] -> [2,32,64,64,64]
// v13: last untested combo — wide loads AND wide store.
// 8 outputs/thread along W: 8x LDG.256 (ld.global.cs.v8.f32) + 1x STG.256
// (st.global.cs.v8.f32). Halves both load- and store-side L1tex wavefront
// queue entries vs v4. Exact grid, no tail guard.

#define W_IN    128
#define HW_IN   (128 * 128)
#define DHW_IN  (128 * 128 * 128)
#define W_OUT   64
#define HW_OUT  (64 * 64)
#define DHW_OUT (64 * 64 * 64)

__device__ __forceinline__ void ldg256_cs(const float* p, float4& a, float4& b)
{
    asm("ld.global.cs.v8.f32 {%0,%1,%2,%3,%4,%5,%6,%7}, [%8];"
        : "=f"(a.x), "=f"(a.y), "=f"(a.z), "=f"(a.w),
          "=f"(b.x), "=f"(b.y), "=f"(b.z), "=f"(b.w)
        : "l"(p));
}

__device__ __forceinline__ void stg256_cs(float* p, const float4& a, const float4& b)
{
    asm volatile("st.global.cs.v8.f32 [%0], {%1,%2,%3,%4,%5,%6,%7,%8};"
        :: "l"(p),
           "f"(a.x), "f"(a.y), "f"(a.z), "f"(a.w),
           "f"(b.x), "f"(b.y), "f"(b.z), "f"(b.w)
        : "memory");
}

// max of a 2-wide window pair reduction: from two float4 covering 8 inputs,
// produce 4 outputs' partials? (handled inline below)

__global__ void __launch_bounds__(512) maxpool3d_k2s2_v13(
    const float* __restrict__ in, float* __restrict__ out)
{
    int tid = blockIdx.x * blockDim.x + threadIdx.x;   // exact grid: no bounds check

    // tid -> (bc, d, h, q), q in [0,8): outputs w = 8q..8q+7
    int q  = tid & 7;
    int t1 = tid >> 3;
    int h  = t1 & 63;
    int t2 = t1 >> 6;
    int d  = t2 & 63;
    int bc = t2 >> 6;            // 0..63

    const float* base = in + (size_t)bc * DHW_IN + (size_t)(2 * d) * HW_IN
                           + (size_t)(2 * h) * W_IN + 16 * q;   // 64B-aligned

    // 4 input rows x 16 floats each (two LDG.256 per row)
    float4 r0a, r0b, r0c, r0d;   // (2d,   2h  ) w: 16q .. 16q+15
    float4 r1a, r1b, r1c, r1d;   // (2d,   2h+1)
    float4 r2a, r2b, r2c, r2d;   // (2d+1, 2h  )
    float4 r3a, r3b, r3c, r3d;   // (2d+1, 2h+1)
    ldg256_cs(base,                    r0a, r0b);
    ldg256_cs(base + 8,                r0c, r0d);
    ldg256_cs(base + W_IN,             r1a, r1b);
    ldg256_cs(base + W_IN + 8,         r1c, r1d);
    ldg256_cs(base + HW_IN,            r2a, r2b);
    ldg256_cs(base + HW_IN + 8,        r2c, r2d);
    ldg256_cs(base + HW_IN + W_IN,     r3a, r3b);
    ldg256_cs(base + HW_IN + W_IN + 8, r3c, r3d);

    // Reduce: out[w] = max over the 2x2x2 window. Pairs along W within each float4.
    float4 o0, o1;   // 8 outputs
    o0.x = fmaxf(fmaxf(fmaxf(r0a.x, r0a.y), fmaxf(r1a.x, r1a.y)),
                 fmaxf(fmaxf(r2a.x, r2a.y), fmaxf(r3a.x, r3a.y)));
    o0.y = fmaxf(fmaxf(fmaxf(r0a.z, r0a.w), fmaxf(r1a.z, r1a.w)),
                 fmaxf(fmaxf(r2a.z, r2a.w), fmaxf(r3a.z, r3a.w)));
    o0.z = fmaxf(fmaxf(fmaxf(r0b.x, r0b.y), fmaxf(r1b.x, r1b.y)),
                 fmaxf(fmaxf(r2b.x, r2b.y), fmaxf(r3b.x, r3b.y)));
    o0.w = fmaxf(fmaxf(fmaxf(r0b.z, r0b.w), fmaxf(r1b.z, r1b.w)),
                 fmaxf(fmaxf(r2b.z, r2b.w), fmaxf(r3b.z, r3b.w)));
    o1.x = fmaxf(fmaxf(fmaxf(r0c.x, r0c.y), fmaxf(r1c.x, r1c.y)),
                 fmaxf(fmaxf(r2c.x, r2c.y), fmaxf(r3c.x, r3c.y)));
    o1.y = fmaxf(fmaxf(fmaxf(r0c.z, r0c.w), fmaxf(r1c.z, r1c.w)),
                 fmaxf(fmaxf(r2c.z, r2c.w), fmaxf(r3c.z, r3c.w)));
    o1.z = fmaxf(fmaxf(fmaxf(r0d.x, r0d.y), fmaxf(r1d.x, r1d.y)),
                 fmaxf(fmaxf(r2d.x, r2d.y), fmaxf(r3d.x, r3d.y)));
    o1.w = fmaxf(fmaxf(fmaxf(r0d.z, r0d.w), fmaxf(r1d.z, r1d.w)),
                 fmaxf(fmaxf(r2d.z, r2d.w), fmaxf(r3d.z, r3d.w)));

    float* op = out + (size_t)bc * DHW_OUT + (size_t)d * HW_OUT + (size_t)h * W_OUT
                    + 8 * q;   // 32B-aligned
    stg256_cs(op, o0, o1);
}

extern "C" void kernel_launch(void* const* d_in, const int* in_sizes, int n_in,
                              void* d_out, int out_size)
{
    const float* in = (const float*)d_in[0];
    float* out = (float*)d_out;
    int n_oct = out_size / 8;                // 2,097,152 (divides 512 exactly)
    maxpool3d_k2s2_v13<<<n_oct / 512, 512>>>(in, out);
}

// round 14
// speedup vs baseline: 1.0260x; 1.0260x over previous
#include <cuda_runtime.h>

// MaxPool3d k=2 s=2 fp32 [2,32,128,128,128] -> [2,32,64,64,64]
// FINAL = R4 best (wall 88.1us, kernel 83.4us, ~7000 GB/s = 88% HBM spec).
// block=512, exact grid (no tail guard), 4 outputs/thread along W,
// 8x float4 streaming loads (__ldcs), 1x float4 streaming store (__stcs).
//
// Full measured knob matrix over 13 rounds:
//   tail-guard removal + block 512 ... best (this kernel)
//   ILP 4->8 outputs (128b loads) .... flat
//   256-bit LDG (4 outputs) .......... flat
//   256-bit LDG+STG (8 outputs) ...... -2.5%
//   block 256 ........................ -1%
//   persistent single-wave ........... -12%
//   __stwt write-through ............. -7%
// DRAM% invariant across occ 57-83%, MLP 4-16, widths 128/256b ->
// the LTS/HBM path is the hard ceiling (~88% of spec) for this 9:1
// read:write stream; traffic is irreducible. Converged.

#define W_IN    128
#define HW_IN   (128 * 128)
#define DHW_IN  (128 * 128 * 128)
#define W_OUT   64
#define HW_OUT  (64 * 64)
#define DHW_OUT (64 * 64 * 64)

__global__ void __launch_bounds__(512) maxpool3d_k2s2_final(
    const float* __restrict__ in, float* __restrict__ out)
{
    int tid = blockIdx.x * blockDim.x + threadIdx.x;   // exact grid: no bounds check

    // tid -> (bc, d, h, q), q in [0,16): outputs w = 4q..4q+3
    int q  = tid & 15;
    int t1 = tid >> 4;
    int h  = t1 & 63;
    int t2 = t1 >> 6;
    int d  = t2 & 63;
    int bc = t2 >> 6;            // 0..63

    const float4* base = reinterpret_cast<const float4*>(
        in + (size_t)bc * DHW_IN + (size_t)(2 * d) * HW_IN + (size_t)(2 * h) * W_IN)
        + 2 * q;

    float4 r0a = __ldcs(base);
    float4 r0b = __ldcs(base + 1);
    float4 r1a = __ldcs(base + (W_IN / 4));
    float4 r1b = __ldcs(base + (W_IN / 4) + 1);
    float4 r2a = __ldcs(base + (HW_IN / 4));
    float4 r2b = __ldcs(base + (HW_IN / 4) + 1);
    float4 r3a = __ldcs(base + (HW_IN / 4 + W_IN / 4));
    float4 r3b = __ldcs(base + (HW_IN / 4 + W_IN / 4) + 1);

    float4 res;
    res.x = fmaxf(fmaxf(fmaxf(r0a.x, r0a.y), fmaxf(r1a.x, r1a.y)),
                  fmaxf(fmaxf(r2a.x, r2a.y), fmaxf(r3a.x, r3a.y)));
    res.y = fmaxf(fmaxf(fmaxf(r0a.z, r0a.w), fmaxf(r1a.z, r1a.w)),
                  fmaxf(fmaxf(r2a.z, r2a.w), fmaxf(r3a.z, r3a.w)));
    res.z = fmaxf(fmaxf(fmaxf(r0b.x, r0b.y), fmaxf(r1b.x, r1b.y)),
                  fmaxf(fmaxf(r2b.x, r2b.y), fmaxf(r3b.x, r3b.y)));
    res.w = fmaxf(fmaxf(fmaxf(r0b.z, r0b.w), fmaxf(r1b.z, r1b.w)),
                  fmaxf(fmaxf(r2b.z, r2b.w), fmaxf(r3b.z, r3b.w)));

    float4* op = reinterpret_cast<float4*>(
        out + (size_t)bc * DHW_OUT + (size_t)d * HW_OUT + (size_t)h * W_OUT) + q;
    __stcs(op, res);
}

extern "C" void kernel_launch(void* const* d_in, const int* in_sizes, int n_in,
                              void* d_out, int out_size)
{
    const float* in = (const float*)d_in[0];
    float* out = (float*)d_out;
    int n_quads = out_size / 4;              // 4,194,304 (divides 512 exactly)
    maxpool3d_k2s2_final<<<n_quads / 512, 512>>>(in, out);
}